// round 7
// baseline (speedup 1.0000x reference)
#include <cuda_runtime.h>
#include <math.h>
#include <stdint.h>

#define H    128
#define NB   64
#define SQ   32
#define SD   256
#define NQTOK (NB*SQ)   // 2048
#define NDTOK (NB*SD)   // 16384

// ---------------- scratch (allocation-free rule) ----------------
__device__ float g_qt[NQTOK*H];   // normalized q, masked, tf32-rounded
__device__ float g_dt[NDTOK*H];   // normalized d, masked, tf32-rounded
__device__ float g_sumq[NB*H];
__device__ float g_sumd[NB*H];
__device__ float g_scores[NB*NB];
__device__ unsigned g_done;       // zero-init; last CTA resets -> replay-safe

// ---------------- helpers ----------------
__device__ __forceinline__ uint32_t smem_u32(const void* p) {
    uint32_t a;
    asm("{ .reg .u64 t; cvta.to.shared.u64 t, %1; cvt.u32.u64 %0, t; }" : "=r"(a) : "l"(p));
    return a;
}
__device__ __forceinline__ float f2tf32(float x) {
    uint32_t r;
    asm("cvt.rna.tf32.f32 %0, %1;" : "=r"(r) : "f"(x));
    return __uint_as_float(r);
}
// rows of 512B (128 tf32 = 32 chunks x 16B); phys chunk = c ^ (row & 7)
__device__ __forceinline__ uint32_t swz(uint32_t base, int row, int chunk) {
    return base + row * 512 + ((chunk ^ (row & 7)) << 4);
}
__device__ __forceinline__ void ldsm_x4(uint32_t& r0, uint32_t& r1, uint32_t& r2, uint32_t& r3,
                                        uint32_t addr) {
    asm volatile("ldmatrix.sync.aligned.m8n8.x4.shared.b16 {%0,%1,%2,%3}, [%4];"
                 : "=r"(r0), "=r"(r1), "=r"(r2), "=r"(r3) : "r"(addr));
}
__device__ __forceinline__ void mma_tf32(float& d0, float& d1, float& d2, float& d3,
                                         uint32_t a0, uint32_t a1, uint32_t a2, uint32_t a3,
                                         uint32_t b0, uint32_t b1) {
    asm volatile("mma.sync.aligned.m16n8k8.row.col.f32.tf32.tf32.f32 "
                 "{%0,%1,%2,%3}, {%4,%5,%6,%7}, {%8,%9}, {%0,%1,%2,%3};"
                 : "+f"(d0), "+f"(d1), "+f"(d2), "+f"(d3)
                 : "r"(a0), "r"(a1), "r"(a2), "r"(a3), "r"(b0), "r"(b1));
}
#define CP_ASYNC16(dst, src) \
    asm volatile("cp.async.cg.shared.global [%0], [%1], 16;" :: "r"(dst), "l"(src))
#define CP_COMMIT() asm volatile("cp.async.commit_group;" ::: "memory")
#define CP_WAIT0()  asm volatile("cp.async.wait_group 0;" ::: "memory")

// ---------------------------------------------------------------------------
// Kernel 1: normalize + mask + tf32 round + per-batch unmasked sums.
// blocks [0,256) = q tokens, [256, 2304) = d tokens. 8 tokens per block.
// ---------------------------------------------------------------------------
__global__ void normsplit_all(const float* __restrict__ qin, const float* __restrict__ din,
                              const int* __restrict__ qm, const int* __restrict__ dm)
{
    __shared__ float red[8 * 128];
    const int blk  = blockIdx.x;
    const int tid  = threadIdx.x;
    const int wid  = tid >> 5;
    const int lane = tid & 31;

    const float* in;  const int* mask;  float* outt;  float* sums;  int tpb, tokbase;
    if (blk < 256) { in = qin; mask = qm; outt = g_qt; sums = g_sumq; tpb = SQ; tokbase = blk * 8; }
    else           { in = din; mask = dm; outt = g_dt; sums = g_sumd; tpb = SD; tokbase = (blk - 256) * 8; }

    const int tok = tokbase + wid;
    float4 v = ((const float4*)in)[tok * 32 + lane];
    float ss = v.x*v.x + v.y*v.y + v.z*v.z + v.w*v.w;
    #pragma unroll
    for (int o = 16; o; o >>= 1) ss += __shfl_xor_sync(0xffffffffu, ss, o);
    float scale = 1.0f / fmaxf(sqrtf(ss), 1e-12f);
    v.x *= scale; v.y *= scale; v.z *= scale; v.w *= scale;

    red[wid * 128 + lane * 4 + 0] = v.x;
    red[wid * 128 + lane * 4 + 1] = v.y;
    red[wid * 128 + lane * 4 + 2] = v.z;
    red[wid * 128 + lane * 4 + 3] = v.w;

    float m = mask[tok] ? 1.0f : 0.0f;
    float4 t;
    t.x = f2tf32(v.x * m); t.y = f2tf32(v.y * m);
    t.z = f2tf32(v.z * m); t.w = f2tf32(v.w * m);
    ((float4*)outt)[tok * 32 + lane] = t;

    __syncthreads();
    if (tid < 128) {
        float s = 0.f;
        #pragma unroll
        for (int w = 0; w < 8; w++) s += red[w * 128 + tid];
        atomicAdd(&sums[(tokbase / tpb) * 128 + tid], s);
    }
}

// ---------------------------------------------------------------------------
// Kernel 2: tf32 max-GEMM (ldmatrix-fed) + fused final loss.
// Grid (16, 8): CTA = (q panel p: 128 rows, d slice s: 2048 rows).
// Q panel resident (64 KB); D streamed as 16 subtiles of 128 rows (64 KB),
// double-buffered. 8 warps, 64x32 warp tiles, m16n8k8 tf32.
// ldmatrix x4 (non-trans) builds both A and B tf32 fragments.
// ---------------------------------------------------------------------------
#define Q_BYTES  (128 * 512)
#define D_BYTES  (128 * 512)
#define SRED_OFF (Q_BYTES + 2 * D_BYTES)
#define SMEM_BYTES (SRED_OFF + 16 * 16 * 4)

__device__ __forceinline__ void cp_tile128(uint32_t dst_u32, const float* __restrict__ src, int tid)
{
    #pragma unroll
    for (int i = 0; i < 16; i++) {
        int id  = i * 256 + tid;       // 4096 chunks: 128 rows x 32 chunks
        int row = id >> 5;
        int ck  = id & 31;
        CP_ASYNC16(swz(dst_u32, row, ck), src + row * 128 + ck * 4);
    }
}

__global__ __launch_bounds__(256, 1) void maxgemm_kernel(float* __restrict__ out)
{
    extern __shared__ char sm[];
    const uint32_t sQ_u32  = smem_u32(sm);
    const uint32_t sD0_u32 = sQ_u32 + Q_BYTES;
    const uint32_t sD1_u32 = sD0_u32 + D_BYTES;
    float* sred = (float*)(sm + SRED_OFF);   // [16 subtiles][4 al][4 wn]

    __shared__ bool  s_last;
    __shared__ float s_avgq[64], s_avgd[64], s_red[64];

    const int p    = blockIdx.x;     // q panel 0..15
    const int s    = blockIdx.y;     // d slice 0..7
    const int tid  = threadIdx.x;    // 256
    const int wid  = tid >> 5;
    const int lane = tid & 31;
    const int wm   = wid >> 2;       // 0..1 -> 64 q rows
    const int wn   = wid & 3;        // 0..3 -> 32 d rows

    // ldmatrix per-lane source row/chunk offsets
    const int a_row = ((lane >> 3) & 1) * 8 + (lane & 7);  // quadrants: (r0,k0),(r8,k0),(r0,k4),(r8,k4)
    const int a_chk = lane >> 4;                            // 0,0,1,1 per 8-lane group
    const int b_row = (lane >> 4) * 8 + (lane & 7);         // quadrants: (n0,k0),(n0,k4),(n8,k0),(n8,k4)
    const int b_chk = (lane >> 3) & 1;

    const float* dbase = g_dt + (size_t)(s * 8) * 256 * H;

    cp_tile128(sQ_u32, g_qt + (size_t)p * 128 * H, tid);
    cp_tile128(sD0_u32, dbase, tid);
    CP_COMMIT();
    CP_WAIT0();
    __syncthreads();

    #pragma unroll 1
    for (int t = 0; t < 16; t++) {
        const uint32_t sB = (t & 1) ? sD1_u32 : sD0_u32;
        if (t < 15) {
            cp_tile128((t & 1) ? sD0_u32 : sD1_u32, dbase + (size_t)(t + 1) * 128 * H, tid);
            CP_COMMIT();
        }

        float acc[4][4][4];
        #pragma unroll
        for (int mt = 0; mt < 4; mt++)
            #pragma unroll
            for (int nb = 0; nb < 4; nb++)
                #pragma unroll
                for (int r = 0; r < 4; r++) acc[mt][nb][r] = 0.f;

        #pragma unroll
        for (int ks = 0; ks < 16; ks++) {
            uint32_t A[4][4], B[2][4];
            #pragma unroll
            for (int mt = 0; mt < 4; mt++)
                ldsm_x4(A[mt][0], A[mt][1], A[mt][2], A[mt][3],
                        swz(sQ_u32, wm * 64 + mt * 16 + a_row, 2 * ks + a_chk));
            #pragma unroll
            for (int np = 0; np < 2; np++)
                ldsm_x4(B[np][0], B[np][1], B[np][2], B[np][3],
                        swz(sB, wn * 32 + np * 16 + b_row, 2 * ks + b_chk));
            #pragma unroll
            for (int mt = 0; mt < 4; mt++)
                #pragma unroll
                for (int np = 0; np < 2; np++) {
                    mma_tf32(acc[mt][2*np][0], acc[mt][2*np][1], acc[mt][2*np][2], acc[mt][2*np][3],
                             A[mt][0], A[mt][1], A[mt][2], A[mt][3], B[np][0], B[np][1]);
                    mma_tf32(acc[mt][2*np+1][0], acc[mt][2*np+1][1], acc[mt][2*np+1][2], acc[mt][2*np+1][3],
                             A[mt][0], A[mt][1], A[mt][2], A[mt][3], B[np][2], B[np][3]);
                }
        }

        // ---- epilogue: subtile t covers d rows of batch b = s*8 + (t>>1) ----
        float m0 = -1e30f, m1 = -1e30f;   // a_local wm*2, wm*2+1
        #pragma unroll
        for (int mt = 0; mt < 4; mt++) {
            float mm = -1e30f;
            #pragma unroll
            for (int nb = 0; nb < 4; nb++)
                #pragma unroll
                for (int r = 0; r < 4; r++) mm = fmaxf(mm, acc[mt][nb][r]);
            if (mt < 2) m0 = fmaxf(m0, mm); else m1 = fmaxf(m1, mm);
        }
        #pragma unroll
        for (int o = 16; o; o >>= 1) {
            m0 = fmaxf(m0, __shfl_xor_sync(0xffffffffu, m0, o));
            m1 = fmaxf(m1, __shfl_xor_sync(0xffffffffu, m1, o));
        }
        if (lane == 0) {
            sred[t * 16 + (wm * 2 + 0) * 4 + wn] = m0;
            sred[t * 16 + (wm * 2 + 1) * 4 + wn] = m1;
        }

        CP_WAIT0();
        __syncthreads();
    }

    if (tid < 32) {
        int bl = tid >> 2;      // batch-local 0..7
        int al = tid & 3;       // a-local 0..3
        float v = -1e30f;
        #pragma unroll
        for (int st = 0; st < 2; st++)
            #pragma unroll
            for (int w = 0; w < 4; w++)
                v = fmaxf(v, sred[(bl * 2 + st) * 16 + al * 4 + w]);
        g_scores[(p * 4 + al) * NB + (s * 8 + bl)] = v;
    }

    // ---- last-CTA fused final reduction ----
    __threadfence();
    __syncthreads();
    if (tid == 0) s_last = (atomicAdd(&g_done, 1u) == 127u);
    __syncthreads();
    if (!s_last) return;
    if (tid == 0) g_done = 0;

    for (int b = wid; b < NB; b += 8) {
        float4 vq = ((const float4*)g_sumq)[b * 32 + lane];
        float4 vd = ((const float4*)g_sumd)[b * 32 + lane];
        float sq = vq.x*vq.x + vq.y*vq.y + vq.z*vq.z + vq.w*vq.w;
        float sd = vd.x*vd.x + vd.y*vd.y + vd.z*vd.z + vd.w*vd.w;
        #pragma unroll
        for (int o = 16; o; o >>= 1) {
            sq += __shfl_xor_sync(0xffffffffu, sq, o);
            sd += __shfl_xor_sync(0xffffffffu, sd, o);
        }
        if (lane == 0) {
            s_avgq[b] = (sq - (float)SQ) * (1.0f / ((float)SQ * (SQ - 1)));
            s_avgd[b] = (sd - (float)SD) * (1.0f / ((float)SD * (SD - 1)));
        }
    }
    __syncthreads();

    #pragma unroll
    for (int r = 0; r < 8; r++) {
        int a = wid * 8 + r;
        float v0 = __ldcg(&g_scores[a * NB + lane]);
        float v1 = __ldcg(&g_scores[a * NB + 32 + lane]);
        float mx = fmaxf(v0, v1);
        #pragma unroll
        for (int o = 16; o; o >>= 1) mx = fmaxf(mx, __shfl_xor_sync(0xffffffffu, mx, o));
        float sum = expf(v0 - mx) + expf(v1 - mx);
        #pragma unroll
        for (int o = 16; o; o >>= 1) sum += __shfl_xor_sync(0xffffffffu, sum, o);
        if (lane == 0) {
            float diag = __ldcg(&g_scores[a * NB + a]);
            s_red[a] = mx + logf(sum) - diag + s_avgq[a] + s_avgd[a];
        }
    }
    __syncthreads();
    if (tid < 32) {
        float v = s_red[tid] + s_red[tid + 32];
        #pragma unroll
        for (int o = 16; o; o >>= 1) v += __shfl_xor_sync(0xffffffffu, v, o);
        if (tid == 0) out[0] = v * (1.0f / NB);
    }
}

// ---------------------------------------------------------------------------
extern "C" void kernel_launch(void* const* d_in, const int* in_sizes, int n_in,
                              void* d_out, int out_size)
{
    const float* q_emb  = (const float*)d_in[0];
    const float* d_emb  = (const float*)d_in[1];
    const int*   q_mask = (const int*)  d_in[2];
    const int*   d_mask = (const int*)  d_in[3];
    float*       out    = (float*)d_out;

    cudaFuncSetAttribute(maxgemm_kernel,
                         cudaFuncAttributeMaxDynamicSharedMemorySize, SMEM_BYTES);

    float *sumq, *sumd;
    cudaGetSymbolAddress((void**)&sumq, g_sumq);
    cudaGetSymbolAddress((void**)&sumd, g_sumd);

    cudaMemsetAsync(sumq, 0, NB * H * sizeof(float));
    cudaMemsetAsync(sumd, 0, NB * H * sizeof(float));
    normsplit_all<<<256 + 2048, 256>>>(q_emb, d_emb, q_mask, d_mask);
    maxgemm_kernel<<<dim3(16, 8), 256, SMEM_BYTES>>>(out);
}